// round 3
// baseline (speedup 1.0000x reference)
#include <cuda_runtime.h>
#include <cuda_bf16.h>
#include <mma.h>

using namespace nvcuda;
typedef __nv_bfloat16 bf16;

#define BATCH 16
#define CDIM  256
#define NTOK  4096
#define MQKV  768
#define KDIM  256

// Static device scratch (allocations are forbidden; __device__ globals are the blessed path)
__device__ __align__(16) bf16  g_xb[(size_t)BATCH * CDIM * NTOK];      // x in bf16
__device__ __align__(16) bf16  g_wqkvb[MQKV * CDIM];                   // w_qkv bf16
__device__ __align__(16) bf16  g_woutb[CDIM * CDIM];                   // w_out bf16
__device__ __align__(16) bf16  g_qkvb[(size_t)BATCH * MQKV * NTOK];    // qkv (k softmaxed in place)
__device__ __align__(16) float g_ctx[BATCH * 4 * 64 * 64];             // context per (b,h)
__device__ __align__(16) bf16  g_outb[(size_t)BATCH * CDIM * NTOK];    // attention output

// ---------------------------------------------------------------------------
// K0: fp32 -> bf16 conversion for x, w_qkv, w_out (vectorized, 4 elems/thread)
// ---------------------------------------------------------------------------
__global__ void convert_kernel(const float* __restrict__ x,
                               const float* __restrict__ wq,
                               const float* __restrict__ wo) {
    size_t i = ((size_t)blockIdx.x * blockDim.x + threadIdx.x) * 4;
    const size_t XT = (size_t)BATCH * CDIM * NTOK;
    const size_t WQ = (size_t)MQKV * CDIM;
    const size_t WO = (size_t)CDIM * CDIM;
    const float* src; bf16* dst; size_t off;
    if (i < XT)                { src = x;  dst = g_xb;    off = i; }
    else if (i < XT + WQ)      { src = wq; dst = g_wqkvb; off = i - XT; }
    else if (i < XT + WQ + WO) { src = wo; dst = g_woutb; off = i - XT - WQ; }
    else return;
    float4 f = *(const float4*)(src + off);
    bf16 __align__(8) t[4] = {__float2bfloat16(f.x), __float2bfloat16(f.y),
                              __float2bfloat16(f.z), __float2bfloat16(f.w)};
    *(uint2*)(dst + off) = *(const uint2*)t;
}

// ---------------------------------------------------------------------------
// K1 / K5: batched GEMM C = A(MxK) @ B(KxN), bf16 in, fp32 accum.
//   mode 0: A=w_qkv (768x256), B=x_bf16[b], C -> g_qkvb (bf16)
//   mode 1: A=w_out (256x256), B=g_outb[b],  C -> y = (acc+b_out)*gamma + x  (fp32)
// Tiles: BM=BN=128, BK=32; 8 warps, each warp computes 64x32 (4x2 wmma tiles).
// ---------------------------------------------------------------------------
__global__ void __launch_bounds__(256) gemm_kernel(int mode,
        const float* __restrict__ bias, const float* __restrict__ gamma,
        const float* __restrict__ xres, float* __restrict__ y) {
    __shared__ __align__(16) char smem[10240 + 8704];   // As[128][40] + Bs[32][136]
    bf16* As = (bf16*)smem;
    bf16* Bs = (bf16*)(smem + 10240);

    const int N = NTOK, K = KDIM;
    const int batch  = blockIdx.z;
    const int blockM = blockIdx.y * 128;
    const int blockN = blockIdx.x * 128;

    const bf16* A = (mode == 0) ? g_wqkvb : g_woutb;
    const bf16* B = ((mode == 0) ? g_xb : g_outb) + (size_t)batch * CDIM * NTOK;

    const int tid = threadIdx.x;
    const int warpId = tid >> 5, lane = tid & 31;
    const int wr = warpId & 1;       // 2 row groups of 64
    const int wc = warpId >> 1;      // 4 col groups of 32

    wmma::fragment<wmma::accumulator, 16, 16, 16, float> acc[4][2];
    #pragma unroll
    for (int i = 0; i < 4; i++)
        #pragma unroll
        for (int j = 0; j < 2; j++) wmma::fill_fragment(acc[i][j], 0.0f);

    for (int k0 = 0; k0 < K; k0 += 32) {
        // Load A tile 128x32 (vec8)
        #pragma unroll
        for (int t = 0; t < 2; t++) {
            int v = tid + t * 256;
            int row = v >> 2, colv = v & 3;
            *(uint4*)(As + row * 40 + colv * 8) =
                *(const uint4*)(A + (size_t)(blockM + row) * K + k0 + colv * 8);
        }
        // Load B tile 32x128 (vec8)
        #pragma unroll
        for (int t = 0; t < 2; t++) {
            int v = tid + t * 256;
            int row = v >> 4, colv = v & 15;
            *(uint4*)(Bs + row * 136 + colv * 8) =
                *(const uint4*)(B + (size_t)(k0 + row) * N + blockN + colv * 8);
        }
        __syncthreads();
        #pragma unroll
        for (int kk = 0; kk < 32; kk += 16) {
            wmma::fragment<wmma::matrix_a, 16, 16, 16, bf16, wmma::row_major> af[4];
            wmma::fragment<wmma::matrix_b, 16, 16, 16, bf16, wmma::row_major> bfr[2];
            #pragma unroll
            for (int i = 0; i < 4; i++)
                wmma::load_matrix_sync(af[i], As + (wr * 64 + i * 16) * 40 + kk, 40);
            #pragma unroll
            for (int j = 0; j < 2; j++)
                wmma::load_matrix_sync(bfr[j], Bs + kk * 136 + wc * 32 + j * 16, 136);
            #pragma unroll
            for (int i = 0; i < 4; i++)
                #pragma unroll
                for (int j = 0; j < 2; j++)
                    wmma::mma_sync(acc[i][j], af[i], bfr[j], acc[i][j]);
        }
        __syncthreads();
    }

    // Epilogue: stage each 16x16 accum tile through (now-free) smem
    float* stage = (float*)smem + warpId * 256;
    const int r = lane >> 1, ch = (lane & 1) * 8;
    #pragma unroll
    for (int i = 0; i < 4; i++) {
        #pragma unroll
        for (int j = 0; j < 2; j++) {
            wmma::store_matrix_sync(stage, acc[i][j], 16, wmma::mem_row_major);
            __syncwarp();
            int grow = blockM + wr * 64 + i * 16 + r;
            int gcol = blockN + wc * 32 + j * 16 + ch;
            const float* s = stage + r * 16 + ch;
            if (mode == 0) {
                bf16 __align__(16) tmp[8];
                #pragma unroll
                for (int t2 = 0; t2 < 8; t2++) tmp[t2] = __float2bfloat16(s[t2]);
                *(uint4*)(g_qkvb + (size_t)batch * MQKV * NTOK + (size_t)grow * N + gcol) =
                    *(const uint4*)tmp;
            } else {
                float bo = bias[grow], ga = gamma[grow];
                const float* xp = xres + (size_t)batch * CDIM * NTOK + (size_t)grow * N + gcol;
                float*       yp = y    + (size_t)batch * CDIM * NTOK + (size_t)grow * N + gcol;
                float o[8];
                #pragma unroll
                for (int t2 = 0; t2 < 8; t2++) o[t2] = fmaf(s[t2] + bo, ga, xp[t2]);
                *(float4*)(yp)     = make_float4(o[0], o[1], o[2], o[3]);
                *(float4*)(yp + 4) = make_float4(o[4], o[5], o[6], o[7]);
            }
            __syncwarp();
        }
    }
}

// ---------------------------------------------------------------------------
// K2: in-place softmax over the k rows of g_qkvb (4096 rows x 4096 elems)
// ---------------------------------------------------------------------------
__global__ void __launch_bounds__(256) softmax_kernel() {
    __shared__ float redm[8], reds[8];
    const int rrow = blockIdx.x;
    const int b = rrow >> 8, c = rrow & 255;
    bf16* row = g_qkvb + ((size_t)b * MQKV + CDIM + c) * NTOK;
    const int tid = threadIdx.x, lane = tid & 31, warp = tid >> 5;

    float v[16];
    float m = -3.0e38f;
    #pragma unroll
    for (int i = 0; i < 16; i++) {
        v[i] = __bfloat162float(row[tid + i * 256]);
        m = fmaxf(m, v[i]);
    }
    #pragma unroll
    for (int o = 16; o; o >>= 1) m = fmaxf(m, __shfl_xor_sync(0xffffffffu, m, o));
    if (lane == 0) redm[warp] = m;
    __syncthreads();
    float mm = redm[0];
    #pragma unroll
    for (int w = 1; w < 8; w++) mm = fmaxf(mm, redm[w]);

    float s = 0.0f;
    #pragma unroll
    for (int i = 0; i < 16; i++) { v[i] = __expf(v[i] - mm); s += v[i]; }
    #pragma unroll
    for (int o = 16; o; o >>= 1) s += __shfl_xor_sync(0xffffffffu, s, o);
    if (lane == 0) reds[warp] = s;
    __syncthreads();
    float ss = 0.0f;
    #pragma unroll
    for (int w = 0; w < 8; w++) ss += reds[w];
    float inv = 1.0f / ss;
    #pragma unroll
    for (int i = 0; i < 16; i++)
        row[tid + i * 256] = __float2bfloat16(v[i] * inv);
}

// ---------------------------------------------------------------------------
// K3: context[b,h] = k_soft(64x4096) @ v^T(4096x64), 64 CTAs, 4 warps each
// ---------------------------------------------------------------------------
__global__ void __launch_bounds__(128) context_kernel() {
    const int bh = blockIdx.x, b = bh >> 2, h = bh & 3;
    const bf16* Kp = g_qkvb + ((size_t)b * MQKV + CDIM     + h * 64) * NTOK;
    const bf16* Vp = g_qkvb + ((size_t)b * MQKV + 2 * CDIM + h * 64) * NTOK;
    const int warp = threadIdx.x >> 5;

    wmma::fragment<wmma::accumulator, 16, 16, 16, float> acc[4];
    #pragma unroll
    for (int j = 0; j < 4; j++) wmma::fill_fragment(acc[j], 0.0f);

    const bf16* Ka = Kp + (size_t)warp * 16 * NTOK;
    for (int kk = 0; kk < NTOK; kk += 16) {
        wmma::fragment<wmma::matrix_a, 16, 16, 16, bf16, wmma::row_major> a;
        wmma::load_matrix_sync(a, Ka + kk, NTOK);
        #pragma unroll
        for (int j = 0; j < 4; j++) {
            wmma::fragment<wmma::matrix_b, 16, 16, 16, bf16, wmma::col_major> bb;
            wmma::load_matrix_sync(bb, Vp + (size_t)j * 16 * NTOK + kk, NTOK);
            wmma::mma_sync(acc[j], a, bb, acc[j]);
        }
    }
    float* base = g_ctx + (size_t)bh * 4096 + warp * 16 * 64;
    #pragma unroll
    for (int j = 0; j < 4; j++)
        wmma::store_matrix_sync(base + j * 16, acc[j], 64, wmma::mem_row_major);
}

// ---------------------------------------------------------------------------
// K4: out[b, h*64+e, n] = sum_d ctx[b,h,d,e] * q[b,h,d,n]   -> g_outb (bf16)
// grid (NTOK/256, BATCH*4), 256 threads; A = ctx^T (64x64), B = q (64x4096)
// ---------------------------------------------------------------------------
__global__ void __launch_bounds__(256) outgemm_kernel() {
    __shared__ __align__(16) char smem[9216 + 33792];   // As[64][72] + Bs[64][264]
    bf16* As = (bf16*)smem;
    bf16* Bs = (bf16*)(smem + 9216);

    const int bh = blockIdx.y, b = bh >> 2, h = bh & 3;
    const int nblk = blockIdx.x;
    const int tid = threadIdx.x;
    const int warpId = tid >> 5, lane = tid & 31;

    // Load ctx (fp32) transposed -> As[e][d] bf16
    #pragma unroll
    for (int t = 0; t < 16; t++) {
        int idx = tid + t * 256;            // idx = d*64 + e
        int d = idx >> 6, e = idx & 63;
        As[e * 72 + d] = __float2bfloat16(g_ctx[(size_t)bh * 4096 + idx]);
    }
    // Load q block 64x256 -> Bs
    const bf16* Qp = g_qkvb + ((size_t)b * MQKV + h * 64) * NTOK + nblk * 256;
    #pragma unroll
    for (int t = 0; t < 8; t++) {
        int v = tid + t * 256;
        int row = v >> 5, colv = v & 31;
        *(uint4*)(Bs + row * 264 + colv * 8) =
            *(const uint4*)(Qp + (size_t)row * NTOK + colv * 8);
    }
    __syncthreads();

    const int wr = warpId & 3;      // 4 row groups of 16 (e)
    const int wc = warpId >> 2;     // 2 col groups of 128 (n)

    wmma::fragment<wmma::accumulator, 16, 16, 16, float> acc[8];
    #pragma unroll
    for (int j = 0; j < 8; j++) wmma::fill_fragment(acc[j], 0.0f);

    #pragma unroll
    for (int kk = 0; kk < 64; kk += 16) {
        wmma::fragment<wmma::matrix_a, 16, 16, 16, bf16, wmma::row_major> a;
        wmma::load_matrix_sync(a, As + wr * 16 * 72 + kk, 72);
        #pragma unroll
        for (int j = 0; j < 8; j++) {
            wmma::fragment<wmma::matrix_b, 16, 16, 16, bf16, wmma::row_major> bb;
            wmma::load_matrix_sync(bb, Bs + kk * 264 + wc * 128 + j * 16, 264);
            wmma::mma_sync(acc[j], a, bb, acc[j]);
        }
    }
    __syncthreads();   // smem reuse for staging

    float* stage = (float*)smem + warpId * 256;
    bf16* Op = g_outb + ((size_t)b * CDIM + h * 64) * NTOK + nblk * 256;
    const int r = lane >> 1, ch = (lane & 1) * 8;
    #pragma unroll
    for (int j = 0; j < 8; j++) {
        wmma::store_matrix_sync(stage, acc[j], 16, wmma::mem_row_major);
        __syncwarp();
        int grow = wr * 16 + r;                     // e within head
        int gcol = wc * 128 + j * 16 + ch;          // n within 256-block
        const float* s = stage + r * 16 + ch;
        bf16 __align__(16) tmp[8];
        #pragma unroll
        for (int t2 = 0; t2 < 8; t2++) tmp[t2] = __float2bfloat16(s[t2]);
        *(uint4*)(Op + (size_t)grow * NTOK + gcol) = *(const uint4*)tmp;
        __syncwarp();
    }
}

// ---------------------------------------------------------------------------
extern "C" void kernel_launch(void* const* d_in, const int* in_sizes, int n_in,
                              void* d_out, int out_size) {
    (void)in_sizes; (void)n_in; (void)out_size;
    const float* x     = (const float*)d_in[0];
    const float* wqkv  = (const float*)d_in[1];
    const float* wout  = (const float*)d_in[2];
    const float* bout  = (const float*)d_in[3];
    const float* gamma = (const float*)d_in[4];
    float* y = (float*)d_out;

    size_t total4 = ((size_t)BATCH * CDIM * NTOK + (size_t)MQKV * CDIM +
                     (size_t)CDIM * CDIM) / 4;
    convert_kernel<<<(unsigned)((total4 + 255) / 256), 256>>>(x, wqkv, wout);
    gemm_kernel<<<dim3(NTOK / 128, MQKV / 128, BATCH), 256>>>(0, nullptr, nullptr, nullptr, nullptr);
    softmax_kernel<<<BATCH * CDIM, 256>>>();
    context_kernel<<<BATCH * 4, 128>>>();
    outgemm_kernel<<<dim3(NTOK / 256, BATCH * 4), 256>>>();
    gemm_kernel<<<dim3(NTOK / 128, CDIM / 128, BATCH), 256>>>(1, bout, gamma, x, y);
}

// round 8
// speedup vs baseline: 2.3009x; 2.3009x over previous
#include <cuda_runtime.h>
#include <cuda_bf16.h>
#include <mma.h>

using namespace nvcuda;
typedef __nv_bfloat16 bf16;

#define BATCH 16
#define CDIM  256
#define NTOK  4096
#define MQKV  768
#define KDIM  256
#define CSPLIT 32           // context split-K: 4096 / 32 = 128 tokens per CTA

// Static device scratch (allocations are forbidden; __device__ globals are the blessed path)
__device__ __align__(16) bf16  g_xb[(size_t)BATCH * CDIM * NTOK];      // x in bf16
__device__ __align__(16) bf16  g_wqkvb[MQKV * CDIM];                   // w_qkv bf16
__device__ __align__(16) bf16  g_woutb[CDIM * CDIM];                   // w_out bf16
__device__ __align__(16) bf16  g_qkvb[(size_t)BATCH * MQKV * NTOK];    // qkv (k softmaxed in place)
__device__ __align__(16) float g_ctxp[(size_t)BATCH * 4 * CSPLIT * 64 * 64]; // split-K partials (32 MB)
__device__ __align__(16) float g_ctx[BATCH * 4 * 64 * 64];             // reduced context per (b,h)
__device__ __align__(16) bf16  g_outb[(size_t)BATCH * CDIM * NTOK];    // attention output

// ---------------------------------------------------------------------------
// K0: fp32 -> bf16 conversion for x, w_qkv, w_out (vectorized, 4 elems/thread)
// ---------------------------------------------------------------------------
__global__ void convert_kernel(const float* __restrict__ x,
                               const float* __restrict__ wq,
                               const float* __restrict__ wo) {
    size_t i = ((size_t)blockIdx.x * blockDim.x + threadIdx.x) * 4;
    const size_t XT = (size_t)BATCH * CDIM * NTOK;
    const size_t WQ = (size_t)MQKV * CDIM;
    const size_t WO = (size_t)CDIM * CDIM;
    const float* src; bf16* dst; size_t off;
    if (i < XT)                { src = x;  dst = g_xb;    off = i; }
    else if (i < XT + WQ)      { src = wq; dst = g_wqkvb; off = i - XT; }
    else if (i < XT + WQ + WO) { src = wo; dst = g_woutb; off = i - XT - WQ; }
    else return;
    float4 f = *(const float4*)(src + off);
    bf16 __align__(8) t[4] = {__float2bfloat16(f.x), __float2bfloat16(f.y),
                              __float2bfloat16(f.z), __float2bfloat16(f.w)};
    *(uint2*)(dst + off) = *(const uint2*)t;
}

// ---------------------------------------------------------------------------
// K1 / K5: batched GEMM C = A(MxK) @ B(KxN), bf16 in, fp32 accum.
//   mode 0: A=w_qkv (768x256), B=x_bf16[b], C -> g_qkvb (bf16)
//   mode 1: A=w_out (256x256), B=g_outb[b],  C -> y = (acc+b_out)*gamma + x  (fp32)
// Tiles: BM=BN=128, BK=32; 8 warps, each warp computes 64x32 (4x2 wmma tiles).
// ---------------------------------------------------------------------------
__global__ void __launch_bounds__(256) gemm_kernel(int mode,
        const float* __restrict__ bias, const float* __restrict__ gamma,
        const float* __restrict__ xres, float* __restrict__ y) {
    __shared__ __align__(16) char smem[10240 + 8704];   // As[128][40] + Bs[32][136]
    bf16* As = (bf16*)smem;
    bf16* Bs = (bf16*)(smem + 10240);

    const int N = NTOK, K = KDIM;
    const int batch  = blockIdx.z;
    const int blockM = blockIdx.y * 128;
    const int blockN = blockIdx.x * 128;

    const bf16* A = (mode == 0) ? g_wqkvb : g_woutb;
    const bf16* B = ((mode == 0) ? g_xb : g_outb) + (size_t)batch * CDIM * NTOK;

    const int tid = threadIdx.x;
    const int warpId = tid >> 5, lane = tid & 31;
    const int wr = warpId & 1;       // 2 row groups of 64
    const int wc = warpId >> 1;      // 4 col groups of 32

    wmma::fragment<wmma::accumulator, 16, 16, 16, float> acc[4][2];
    #pragma unroll
    for (int i = 0; i < 4; i++)
        #pragma unroll
        for (int j = 0; j < 2; j++) wmma::fill_fragment(acc[i][j], 0.0f);

    for (int k0 = 0; k0 < K; k0 += 32) {
        // Load A tile 128x32 (vec8)
        #pragma unroll
        for (int t = 0; t < 2; t++) {
            int v = tid + t * 256;
            int row = v >> 2, colv = v & 3;
            *(uint4*)(As + row * 40 + colv * 8) =
                *(const uint4*)(A + (size_t)(blockM + row) * K + k0 + colv * 8);
        }
        // Load B tile 32x128 (vec8)
        #pragma unroll
        for (int t = 0; t < 2; t++) {
            int v = tid + t * 256;
            int row = v >> 4, colv = v & 15;
            *(uint4*)(Bs + row * 136 + colv * 8) =
                *(const uint4*)(B + (size_t)(k0 + row) * N + blockN + colv * 8);
        }
        __syncthreads();
        #pragma unroll
        for (int kk = 0; kk < 32; kk += 16) {
            wmma::fragment<wmma::matrix_a, 16, 16, 16, bf16, wmma::row_major> af[4];
            wmma::fragment<wmma::matrix_b, 16, 16, 16, bf16, wmma::row_major> bfr[2];
            #pragma unroll
            for (int i = 0; i < 4; i++)
                wmma::load_matrix_sync(af[i], As + (wr * 64 + i * 16) * 40 + kk, 40);
            #pragma unroll
            for (int j = 0; j < 2; j++)
                wmma::load_matrix_sync(bfr[j], Bs + kk * 136 + wc * 32 + j * 16, 136);
            #pragma unroll
            for (int i = 0; i < 4; i++)
                #pragma unroll
                for (int j = 0; j < 2; j++)
                    wmma::mma_sync(acc[i][j], af[i], bfr[j], acc[i][j]);
        }
        __syncthreads();
    }

    // Epilogue: stage each 16x16 accum tile through (now-free) smem
    float* stage = (float*)smem + warpId * 256;
    const int r = lane >> 1, ch = (lane & 1) * 8;
    #pragma unroll
    for (int i = 0; i < 4; i++) {
        #pragma unroll
        for (int j = 0; j < 2; j++) {
            wmma::store_matrix_sync(stage, acc[i][j], 16, wmma::mem_row_major);
            __syncwarp();
            int grow = blockM + wr * 64 + i * 16 + r;
            int gcol = blockN + wc * 32 + j * 16 + ch;
            const float* s = stage + r * 16 + ch;
            if (mode == 0) {
                bf16 __align__(16) tmp[8];
                #pragma unroll
                for (int t2 = 0; t2 < 8; t2++) tmp[t2] = __float2bfloat16(s[t2]);
                *(uint4*)(g_qkvb + (size_t)batch * MQKV * NTOK + (size_t)grow * N + gcol) =
                    *(const uint4*)tmp;
            } else {
                float bo = bias[grow], ga = gamma[grow];
                const float* xp = xres + (size_t)batch * CDIM * NTOK + (size_t)grow * N + gcol;
                float*       yp = y    + (size_t)batch * CDIM * NTOK + (size_t)grow * N + gcol;
                float o[8];
                #pragma unroll
                for (int t2 = 0; t2 < 8; t2++) o[t2] = fmaf(s[t2] + bo, ga, xp[t2]);
                *(float4*)(yp)     = make_float4(o[0], o[1], o[2], o[3]);
                *(float4*)(yp + 4) = make_float4(o[4], o[5], o[6], o[7]);
            }
            __syncwarp();
        }
    }
}

// ---------------------------------------------------------------------------
// K2: in-place softmax over the k rows of g_qkvb (4096 rows x 4096 elems)
// ---------------------------------------------------------------------------
__global__ void __launch_bounds__(256) softmax_kernel() {
    __shared__ float redm[8], reds[8];
    const int rrow = blockIdx.x;
    const int b = rrow >> 8, c = rrow & 255;
    bf16* row = g_qkvb + ((size_t)b * MQKV + CDIM + c) * NTOK;
    const int tid = threadIdx.x, lane = tid & 31, warp = tid >> 5;

    float v[16];
    float m = -3.0e38f;
    #pragma unroll
    for (int i = 0; i < 16; i++) {
        v[i] = __bfloat162float(row[tid + i * 256]);
        m = fmaxf(m, v[i]);
    }
    #pragma unroll
    for (int o = 16; o; o >>= 1) m = fmaxf(m, __shfl_xor_sync(0xffffffffu, m, o));
    if (lane == 0) redm[warp] = m;
    __syncthreads();
    float mm = redm[0];
    #pragma unroll
    for (int w = 1; w < 8; w++) mm = fmaxf(mm, redm[w]);

    float s = 0.0f;
    #pragma unroll
    for (int i = 0; i < 16; i++) { v[i] = __expf(v[i] - mm); s += v[i]; }
    #pragma unroll
    for (int o = 16; o; o >>= 1) s += __shfl_xor_sync(0xffffffffu, s, o);
    if (lane == 0) reds[warp] = s;
    __syncthreads();
    float ss = 0.0f;
    #pragma unroll
    for (int w = 0; w < 8; w++) ss += reds[w];
    float inv = 1.0f / ss;
    #pragma unroll
    for (int i = 0; i < 16; i++)
        row[tid + i * 256] = __float2bfloat16(v[i] * inv);
}

// ---------------------------------------------------------------------------
// K3a: split-K context partials.
//   grid (CSPLIT, BATCH*4), 128 threads (4 warps).
//   Each CTA: partial[bh][sp] (64x64 fp32) = K[64, 128tok] @ V^T[128tok, 64]
//   K/V chunks staged through smem with coalesced vec8 loads.
// ---------------------------------------------------------------------------
__global__ void __launch_bounds__(128) context_part_kernel() {
    __shared__ __align__(16) bf16 Ks[64 * 136];
    __shared__ __align__(16) bf16 Vs[64 * 136];

    const int sp = blockIdx.x;              // token split index
    const int bh = blockIdx.y, b = bh >> 2, h = bh & 3;
    const int tid = threadIdx.x;
    const int warp = tid >> 5;
    const int TOK0 = sp * (NTOK / CSPLIT);  // 128 tokens per split

    const bf16* Kp = g_qkvb + ((size_t)b * MQKV + CDIM     + h * 64) * NTOK + TOK0;
    const bf16* Vp = g_qkvb + ((size_t)b * MQKV + 2 * CDIM + h * 64) * NTOK + TOK0;

    // 64 rows x 128 cols bf16 = 64 x 16 uint4 per operand; 8 uint4 per thread
    #pragma unroll
    for (int t = 0; t < 8; t++) {
        int v = tid + t * 128;
        int row = v >> 4, colv = v & 15;
        *(uint4*)(Ks + row * 136 + colv * 8) =
            *(const uint4*)(Kp + (size_t)row * NTOK + colv * 8);
        *(uint4*)(Vs + row * 136 + colv * 8) =
            *(const uint4*)(Vp + (size_t)row * NTOK + colv * 8);
    }
    __syncthreads();

    // warp computes rows [warp*16, warp*16+16) of the 64x64 partial
    wmma::fragment<wmma::accumulator, 16, 16, 16, float> acc[4];
    #pragma unroll
    for (int j = 0; j < 4; j++) wmma::fill_fragment(acc[j], 0.0f);

    #pragma unroll
    for (int kk = 0; kk < 128; kk += 16) {
        wmma::fragment<wmma::matrix_a, 16, 16, 16, bf16, wmma::row_major> a;
        wmma::load_matrix_sync(a, Ks + (warp * 16) * 136 + kk, 136);
        #pragma unroll
        for (int j = 0; j < 4; j++) {
            wmma::fragment<wmma::matrix_b, 16, 16, 16, bf16, wmma::col_major> bb;
            wmma::load_matrix_sync(bb, Vs + (j * 16) * 136 + kk, 136);
            wmma::mma_sync(acc[j], a, bb, acc[j]);
        }
    }

    float* base = g_ctxp + ((size_t)bh * CSPLIT + sp) * 4096 + warp * 16 * 64;
    #pragma unroll
    for (int j = 0; j < 4; j++)
        wmma::store_matrix_sync(base + j * 16, acc[j], 64, wmma::mem_row_major);
}

// ---------------------------------------------------------------------------
// K3b: reduce the CSPLIT partials -> g_ctx. Fixed summation order (deterministic).
//   grid (BATCH*4), 256 threads, 16 elements each.
// ---------------------------------------------------------------------------
__global__ void __launch_bounds__(256) context_reduce_kernel() {
    const int bh = blockIdx.x;
    const int tid = threadIdx.x;
    const float* src = g_ctxp + (size_t)bh * CSPLIT * 4096;
    float* dst = g_ctx + (size_t)bh * 4096;
    #pragma unroll
    for (int t = 0; t < 16; t++) {
        int idx = tid + t * 256;
        float s = 0.0f;
        #pragma unroll
        for (int sp = 0; sp < CSPLIT; sp++)
            s += src[(size_t)sp * 4096 + idx];
        dst[idx] = s;
    }
}

// ---------------------------------------------------------------------------
// K4: out[b, h*64+e, n] = sum_d ctx[b,h,d,e] * q[b,h,d,n]   -> g_outb (bf16)
// grid (NTOK/256, BATCH*4), 256 threads; A = ctx^T (64x64), B = q (64x4096)
// ---------------------------------------------------------------------------
__global__ void __launch_bounds__(256) outgemm_kernel() {
    __shared__ __align__(16) char smem[9216 + 33792];   // As[64][72] + Bs[64][264]
    bf16* As = (bf16*)smem;
    bf16* Bs = (bf16*)(smem + 9216);

    const int bh = blockIdx.y, b = bh >> 2, h = bh & 3;
    const int nblk = blockIdx.x;
    const int tid = threadIdx.x;
    const int warpId = tid >> 5, lane = tid & 31;

    // Load ctx (fp32) transposed -> As[e][d] bf16
    #pragma unroll
    for (int t = 0; t < 16; t++) {
        int idx = tid + t * 256;            // idx = d*64 + e
        int d = idx >> 6, e = idx & 63;
        As[e * 72 + d] = __float2bfloat16(g_ctx[(size_t)bh * 4096 + idx]);
    }
    // Load q block 64x256 -> Bs
    const bf16* Qp = g_qkvb + ((size_t)b * MQKV + h * 64) * NTOK + nblk * 256;
    #pragma unroll
    for (int t = 0; t < 8; t++) {
        int v = tid + t * 256;
        int row = v >> 5, colv = v & 31;
        *(uint4*)(Bs + row * 264 + colv * 8) =
            *(const uint4*)(Qp + (size_t)row * NTOK + colv * 8);
    }
    __syncthreads();

    const int wr = warpId & 3;      // 4 row groups of 16 (e)
    const int wc = warpId >> 2;     // 2 col groups of 128 (n)

    wmma::fragment<wmma::accumulator, 16, 16, 16, float> acc[8];
    #pragma unroll
    for (int j = 0; j < 8; j++) wmma::fill_fragment(acc[j], 0.0f);

    #pragma unroll
    for (int kk = 0; kk < 64; kk += 16) {
        wmma::fragment<wmma::matrix_a, 16, 16, 16, bf16, wmma::row_major> a;
        wmma::load_matrix_sync(a, As + wr * 16 * 72 + kk, 72);
        #pragma unroll
        for (int j = 0; j < 8; j++) {
            wmma::fragment<wmma::matrix_b, 16, 16, 16, bf16, wmma::row_major> bb;
            wmma::load_matrix_sync(bb, Bs + kk * 264 + wc * 128 + j * 16, 264);
            wmma::mma_sync(acc[j], a, bb, acc[j]);
        }
    }
    __syncthreads();   // smem reuse for staging

    float* stage = (float*)smem + warpId * 256;
    bf16* Op = g_outb + ((size_t)b * CDIM + h * 64) * NTOK + nblk * 256;
    const int r = lane >> 1, ch = (lane & 1) * 8;
    #pragma unroll
    for (int j = 0; j < 8; j++) {
        wmma::store_matrix_sync(stage, acc[j], 16, wmma::mem_row_major);
        __syncwarp();
        int grow = wr * 16 + r;                     // e within head
        int gcol = wc * 128 + j * 16 + ch;          // n within 256-block
        const float* s = stage + r * 16 + ch;
        bf16 __align__(16) tmp[8];
        #pragma unroll
        for (int t2 = 0; t2 < 8; t2++) tmp[t2] = __float2bfloat16(s[t2]);
        *(uint4*)(Op + (size_t)grow * NTOK + gcol) = *(const uint4*)tmp;
        __syncwarp();
    }
}

// ---------------------------------------------------------------------------
extern "C" void kernel_launch(void* const* d_in, const int* in_sizes, int n_in,
                              void* d_out, int out_size) {
    (void)in_sizes; (void)n_in; (void)out_size;
    const float* x     = (const float*)d_in[0];
    const float* wqkv  = (const float*)d_in[1];
    const float* wout  = (const float*)d_in[2];
    const float* bout  = (const float*)d_in[3];
    const float* gamma = (const float*)d_in[4];
    float* y = (float*)d_out;

    size_t total4 = ((size_t)BATCH * CDIM * NTOK + (size_t)MQKV * CDIM +
                     (size_t)CDIM * CDIM) / 4;
    convert_kernel<<<(unsigned)((total4 + 255) / 256), 256>>>(x, wqkv, wout);
    gemm_kernel<<<dim3(NTOK / 128, MQKV / 128, BATCH), 256>>>(0, nullptr, nullptr, nullptr, nullptr);
    softmax_kernel<<<BATCH * CDIM, 256>>>();
    context_part_kernel<<<dim3(CSPLIT, BATCH * 4), 128>>>();
    context_reduce_kernel<<<BATCH * 4, 256>>>();
    outgemm_kernel<<<dim3(NTOK / 256, BATCH * 4), 256>>>();
    gemm_kernel<<<dim3(NTOK / 128, CDIM / 128, BATCH), 256>>>(1, bout, gamma, x, y);
}